// round 4
// baseline (speedup 1.0000x reference)
#include <cuda_runtime.h>

// NeighborList: all i<j pairs, minimum-image PBC, cutoff mask.
// Output (float32): [0,P) pair_i | [P,2P) pair_j | [2P,5P) deltas[P,3] | [5P,6P) dist

#define MAXN 8192
#define TPB  256
#define UPT  8          // pairs per thread

__device__ float g_x[MAXN], g_y[MAXN], g_z[MAXN];
__device__ float g_inv[9];
__device__ float g_cellm[9];
__device__ int   g_cell_zero;

// Fused prep: thread (0,0) inverts the cell; all threads transpose xyz -> SoA.
__global__ void prep_kernel(const float* __restrict__ xyz,
                            const float* __restrict__ cell, int n) {
    const int k = blockIdx.x * blockDim.x + threadIdx.x;
    if (k < n) {
        g_x[k] = xyz[3 * k + 0];
        g_y[k] = xyz[3 * k + 1];
        g_z[k] = xyz[3 * k + 2];
    }
    if (blockIdx.x == 0 && threadIdx.x == 0) {
        bool zero = true;
        float c[9];
#pragma unroll
        for (int q = 0; q < 9; q++) {
            c[q] = cell[q];
            if (c[q] != 0.0f) zero = false;
        }
        if (zero) {
            c[0] = c[4] = c[8] = 1.0f;
            c[1] = c[2] = c[3] = c[5] = c[6] = c[7] = 0.0f;
        }
#pragma unroll
        for (int q = 0; q < 9; q++) g_cellm[q] = c[q];

        float a = c[0], b = c[1], cc = c[2];
        float d = c[3], e = c[4], f  = c[5];
        float g = c[6], h = c[7], i  = c[8];
        float A =  (e * i - f * h);
        float B = -(d * i - f * g);
        float C =  (d * h - e * g);
        float det = a * A + b * B + cc * C;
        float invdet = 1.0f / det;
        g_inv[0] = A * invdet;
        g_inv[1] = -(b * i - cc * h) * invdet;
        g_inv[2] =  (b * f - cc * e) * invdet;
        g_inv[3] = B * invdet;
        g_inv[4] =  (a * i - cc * g) * invdet;
        g_inv[5] = -(a * f - cc * d) * invdet;
        g_inv[6] = C * invdet;
        g_inv[7] = -(a * h - b * g) * invdet;
        g_inv[8] =  (a * e - b * d) * invdet;
        g_cell_zero = zero ? 1 : 0;
    }
}

__device__ __forceinline__ unsigned tri_off(unsigned i, unsigned T) {
    return (i * (T - i)) >> 1;   // i*(2n-1-i)/2
}

__global__ void __launch_bounds__(TPB)
nl_kernel(float* __restrict__ out, int n, unsigned P) {
    const unsigned t = blockIdx.x * TPB + threadIdx.x;
    const unsigned p = UPT * t;
    if (p >= P) return;

    const unsigned T = 2u * (unsigned)n - 1u;

    // ---- unrank p -> (i, j) ----
    const unsigned D = T * T - 8u * p;
    const float s = sqrtf((float)D);
    int i = (int)(((float)T - s) * 0.5f);
    if (i < 0) i = 0;
    if (i > n - 2) i = n - 2;
    unsigned offi = tri_off((unsigned)i, T);
    while (offi > p) { i--; offi = tri_off((unsigned)i, T); }
    unsigned rowend = tri_off((unsigned)(i + 1), T);
    while (rowend <= p && i < n - 2) {
        i++; offi = rowend; rowend = tri_off((unsigned)(i + 1), T);
    }
    int j = i + 1 + (int)(p - offi);

    // ---- hoist cell matrices into registers ----
    const int czero = g_cell_zero;
    float inv[9], cel[9];
    if (!czero) {
#pragma unroll
        for (int q = 0; q < 9; q++) { inv[q] = g_inv[q]; cel[q] = g_cellm[q]; }
    }

    float xi = g_x[i], yi = g_y[i], zi = g_z[i];

    float oi[UPT], oj[UPT], od[UPT], del[3 * UPT];
    const unsigned nv = (P - p < (unsigned)UPT) ? (P - p) : (unsigned)UPT;

#pragma unroll
    for (int k = 0; k < UPT; k++) {
        if ((unsigned)k >= nv) { oi[k] = oj[k] = od[k] = 0.0f;
                                 del[3*k] = del[3*k+1] = del[3*k+2] = 0.0f; continue; }
        if (p + (unsigned)k == rowend) {        // row crossing (rare)
            i++; j = i + 1;
            rowend = tri_off((unsigned)(i + 1), T);
            xi = g_x[i]; yi = g_y[i]; zi = g_z[i];
        }

        float dx = xi - g_x[j];
        float dy = yi - g_y[j];
        float dz = zi - g_z[j];

        if (!czero) {
            const float f0 = dx * inv[0] + dy * inv[3] + dz * inv[6];
            const float f1 = dx * inv[1] + dy * inv[4] + dz * inv[7];
            const float f2 = dx * inv[2] + dy * inv[5] + dz * inv[8];
            const float r0 = rintf(f0);   // jnp.round = half-to-even
            const float r1 = rintf(f1);
            const float r2 = rintf(f2);
            dx -= r0 * cel[0] + r1 * cel[3] + r2 * cel[6];
            dy -= r0 * cel[1] + r1 * cel[4] + r2 * cel[7];
            dz -= r0 * cel[2] + r1 * cel[5] + r2 * cel[8];
        }

        const float dist = sqrtf(dx * dx + dy * dy + dz * dz);
        const bool m = (dist <= 5.0f);

        oi[k] = m ? (float)i : -1.0f;
        oj[k] = m ? (float)j : -1.0f;
        od[k] = m ? dist : 0.0f;
        del[3*k + 0] = m ? dx : 0.0f;
        del[3*k + 1] = m ? dy : 0.0f;
        del[3*k + 2] = m ? dz : 0.0f;
        j++;
    }

    if (nv == (unsigned)UPT) {
        // All 16B-aligned: P % 8 == 0, p % 8 == 0. Streaming (evict-first) stores.
        __stcs(reinterpret_cast<float4*>(out + p),
               make_float4(oi[0], oi[1], oi[2], oi[3]));
        __stcs(reinterpret_cast<float4*>(out + p + 4),
               make_float4(oi[4], oi[5], oi[6], oi[7]));
        __stcs(reinterpret_cast<float4*>(out + (size_t)P + p),
               make_float4(oj[0], oj[1], oj[2], oj[3]));
        __stcs(reinterpret_cast<float4*>(out + (size_t)P + p + 4),
               make_float4(oj[4], oj[5], oj[6], oj[7]));
        __stcs(reinterpret_cast<float4*>(out + 5 * (size_t)P + p),
               make_float4(od[0], od[1], od[2], od[3]));
        __stcs(reinterpret_cast<float4*>(out + 5 * (size_t)P + p + 4),
               make_float4(od[4], od[5], od[6], od[7]));
        float* db = out + 2 * (size_t)P + 3 * (size_t)p;   // byte off 8P+96t, 16B-aligned
#pragma unroll
        for (int q = 0; q < 6; q++) {
            __stcs(reinterpret_cast<float4*>(db + 4 * q),
                   make_float4(del[4*q], del[4*q+1], del[4*q+2], del[4*q+3]));
        }
    } else {
        for (unsigned k = 0; k < nv; k++) {
            out[p + k]                 = oi[k];
            out[(size_t)P + p + k]     = oj[k];
            out[5 * (size_t)P + p + k] = od[k];
            out[2 * (size_t)P + 3 * ((size_t)p + k) + 0] = del[3*k + 0];
            out[2 * (size_t)P + 3 * ((size_t)p + k) + 1] = del[3*k + 1];
            out[2 * (size_t)P + 3 * ((size_t)p + k) + 2] = del[3*k + 2];
        }
    }
}

extern "C" void kernel_launch(void* const* d_in, const int* in_sizes, int n_in,
                              void* d_out, int out_size) {
    const float* xyz  = (const float*)d_in[0];
    const float* cell = (const float*)d_in[1];
    if (n_in >= 2 && in_sizes[0] == 9 && in_sizes[1] != 9) {
        const float* t = xyz; xyz = cell; cell = t;
    }
    const int n = (in_sizes[0] == 9 && n_in >= 2) ? in_sizes[1] / 3 : in_sizes[0] / 3;
    const unsigned P = (unsigned)((size_t)n * (size_t)(n - 1) / 2);

    prep_kernel<<<(n + TPB - 1) / TPB, TPB>>>(xyz, cell, n);

    const unsigned nthreads = (P + UPT - 1) / UPT;
    const unsigned blocks = (nthreads + TPB - 1) / TPB;
    nl_kernel<<<blocks, TPB>>>((float*)d_out, n, P);
}

// round 5
// speedup vs baseline: 1.2534x; 1.2534x over previous
#include <cuda_runtime.h>

// NeighborList: all i<j pairs, minimum-image PBC, cutoff mask.
// Output (float32): [0,P) pair_i | [P,2P) pair_j | [2P,5P) deltas[P,3] | [5P,6P) dist

#define MAXN 8192
#define TPB  256

__device__ float g_x[MAXN], g_y[MAXN], g_z[MAXN];
__device__ float g_inv[9];
__device__ float g_cellm[9];
__device__ int   g_cell_zero;

// Fused prep: thread (0,0) inverts the cell; all threads transpose xyz -> SoA.
__global__ void prep_kernel(const float* __restrict__ xyz,
                            const float* __restrict__ cell, int n) {
    const int k = blockIdx.x * blockDim.x + threadIdx.x;
    if (k < n) {
        g_x[k] = xyz[3 * k + 0];
        g_y[k] = xyz[3 * k + 1];
        g_z[k] = xyz[3 * k + 2];
    }
    if (blockIdx.x == 0 && threadIdx.x == 0) {
        bool zero = true;
        float c[9];
#pragma unroll
        for (int q = 0; q < 9; q++) {
            c[q] = cell[q];
            if (c[q] != 0.0f) zero = false;
        }
        if (zero) {
            c[0] = c[4] = c[8] = 1.0f;
            c[1] = c[2] = c[3] = c[5] = c[6] = c[7] = 0.0f;
        }
#pragma unroll
        for (int q = 0; q < 9; q++) g_cellm[q] = c[q];

        float a = c[0], b = c[1], cc = c[2];
        float d = c[3], e = c[4], f  = c[5];
        float g = c[6], h = c[7], i  = c[8];
        float A =  (e * i - f * h);
        float B = -(d * i - f * g);
        float C =  (d * h - e * g);
        float det = a * A + b * B + cc * C;
        float invdet = 1.0f / det;
        g_inv[0] = A * invdet;
        g_inv[1] = -(b * i - cc * h) * invdet;
        g_inv[2] =  (b * f - cc * e) * invdet;
        g_inv[3] = B * invdet;
        g_inv[4] =  (a * i - cc * g) * invdet;
        g_inv[5] = -(a * f - cc * d) * invdet;
        g_inv[6] = C * invdet;
        g_inv[7] = -(a * h - b * g) * invdet;
        g_inv[8] =  (a * e - b * d) * invdet;
        g_cell_zero = zero ? 1 : 0;
    }
}

__device__ __forceinline__ unsigned tri_off(unsigned i, unsigned T) {
    return (i * (T - i)) >> 1;   // i*(2n-1-i)/2
}

__global__ void __launch_bounds__(TPB, 8)
nl_kernel(float* __restrict__ out, int n, unsigned P) {
    const unsigned t = blockIdx.x * TPB + threadIdx.x;
    const unsigned p = 4u * t;
    if (p >= P) return;

    const unsigned T = 2u * (unsigned)n - 1u;

    // ---- unrank p -> (i, j) ----
    const unsigned D = T * T - 8u * p;
    const float s = sqrtf((float)D);
    int i = (int)(((float)T - s) * 0.5f);
    if (i < 0) i = 0;
    if (i > n - 2) i = n - 2;
    unsigned offi = tri_off((unsigned)i, T);
    while (offi > p) { i--; offi = tri_off((unsigned)i, T); }
    unsigned rowend = tri_off((unsigned)(i + 1), T);
    while (rowend <= p && i < n - 2) {
        i++; offi = rowend; rowend = tri_off((unsigned)(i + 1), T);
    }
    int j = i + 1 + (int)(p - offi);

    // ---- hoist cell matrices into registers (once per 4 pairs) ----
    const int czero = g_cell_zero;
    float inv[9], cel[9];
    if (!czero) {
#pragma unroll
        for (int q = 0; q < 9; q++) { inv[q] = g_inv[q]; cel[q] = g_cellm[q]; }
    }

    float xi = g_x[i], yi = g_y[i], zi = g_z[i];

    float oi[4], oj[4], od[4], del[12];
    const unsigned nv = (P - p < 4u) ? (P - p) : 4u;

#pragma unroll
    for (int k = 0; k < 4; k++) {
        if ((unsigned)k >= nv) { oi[k] = oj[k] = od[k] = 0.0f;
                                 del[3*k] = del[3*k+1] = del[3*k+2] = 0.0f; continue; }
        if (p + (unsigned)k == rowend) {        // row crossing (rare)
            i++; j = i + 1;
            rowend = tri_off((unsigned)(i + 1), T);
            xi = g_x[i]; yi = g_y[i]; zi = g_z[i];
        }

        float dx = xi - g_x[j];
        float dy = yi - g_y[j];
        float dz = zi - g_z[j];

        if (!czero) {
            const float f0 = dx * inv[0] + dy * inv[3] + dz * inv[6];
            const float f1 = dx * inv[1] + dy * inv[4] + dz * inv[7];
            const float f2 = dx * inv[2] + dy * inv[5] + dz * inv[8];
            const float r0 = rintf(f0);   // jnp.round = half-to-even
            const float r1 = rintf(f1);
            const float r2 = rintf(f2);
            dx -= r0 * cel[0] + r1 * cel[3] + r2 * cel[6];
            dy -= r0 * cel[1] + r1 * cel[4] + r2 * cel[7];
            dz -= r0 * cel[2] + r1 * cel[5] + r2 * cel[8];
        }

        const float dist = sqrtf(dx * dx + dy * dy + dz * dz);
        const bool m = (dist <= 5.0f);

        oi[k] = m ? (float)i : -1.0f;
        oj[k] = m ? (float)j : -1.0f;
        od[k] = m ? dist : 0.0f;
        del[3*k + 0] = m ? dx : 0.0f;
        del[3*k + 1] = m ? dy : 0.0f;
        del[3*k + 2] = m ? dz : 0.0f;
        j++;
    }

    if (nv == 4u) {
        // all vector stores are 16B-aligned: P % 4 == 0, p % 4 == 0
        *reinterpret_cast<float4*>(out + p) =
            make_float4(oi[0], oi[1], oi[2], oi[3]);
        *reinterpret_cast<float4*>(out + (size_t)P + p) =
            make_float4(oj[0], oj[1], oj[2], oj[3]);
        *reinterpret_cast<float4*>(out + 5 * (size_t)P + p) =
            make_float4(od[0], od[1], od[2], od[3]);
        float* db = out + 2 * (size_t)P + 3 * (size_t)p;   // byte off 8P+48t, 16B-aligned
        *reinterpret_cast<float4*>(db + 0) = make_float4(del[0], del[1], del[2],  del[3]);
        *reinterpret_cast<float4*>(db + 4) = make_float4(del[4], del[5], del[6],  del[7]);
        *reinterpret_cast<float4*>(db + 8) = make_float4(del[8], del[9], del[10], del[11]);
    } else {
        for (unsigned k = 0; k < nv; k++) {
            out[p + k]                 = oi[k];
            out[(size_t)P + p + k]     = oj[k];
            out[5 * (size_t)P + p + k] = od[k];
            out[2 * (size_t)P + 3 * ((size_t)p + k) + 0] = del[3*k + 0];
            out[2 * (size_t)P + 3 * ((size_t)p + k) + 1] = del[3*k + 1];
            out[2 * (size_t)P + 3 * ((size_t)p + k) + 2] = del[3*k + 2];
        }
    }
}

extern "C" void kernel_launch(void* const* d_in, const int* in_sizes, int n_in,
                              void* d_out, int out_size) {
    const float* xyz  = (const float*)d_in[0];
    const float* cell = (const float*)d_in[1];
    if (n_in >= 2 && in_sizes[0] == 9 && in_sizes[1] != 9) {
        const float* t = xyz; xyz = cell; cell = t;
    }
    const int n = (in_sizes[0] == 9 && n_in >= 2) ? in_sizes[1] / 3 : in_sizes[0] / 3;
    const unsigned P = (unsigned)((size_t)n * (size_t)(n - 1) / 2);

    prep_kernel<<<(n + TPB - 1) / TPB, TPB>>>(xyz, cell, n);

    const unsigned nthreads = (P + 3) / 4;
    const unsigned blocks = (nthreads + TPB - 1) / TPB;
    nl_kernel<<<blocks, TPB>>>((float*)d_out, n, P);
}

// round 6
// speedup vs baseline: 1.4797x; 1.1805x over previous
#include <cuda_runtime.h>

// NeighborList: all i<j pairs, minimum-image PBC, cutoff mask.
// Output (float32): [0,P) pair_i | [P,2P) pair_j | [2P,5P) deltas[P,3] | [5P,6P) dist

#define MAXN 8192
#define TPB  256

__device__ float g_x[MAXN], g_y[MAXN], g_z[MAXN];
__device__ float g_inv[9];
__device__ float g_cellm[9];
__device__ int   g_cell_zero;

// Fused prep: thread (0,0) inverts the cell; all threads transpose xyz -> SoA.
__global__ void prep_kernel(const float* __restrict__ xyz,
                            const float* __restrict__ cell, int n) {
    const int k = blockIdx.x * blockDim.x + threadIdx.x;
    if (k < n) {
        g_x[k] = xyz[3 * k + 0];
        g_y[k] = xyz[3 * k + 1];
        g_z[k] = xyz[3 * k + 2];
    }
    if (blockIdx.x == 0 && threadIdx.x == 0) {
        bool zero = true;
        float c[9];
#pragma unroll
        for (int q = 0; q < 9; q++) {
            c[q] = cell[q];
            if (c[q] != 0.0f) zero = false;
        }
        if (zero) {
            c[0] = c[4] = c[8] = 1.0f;
            c[1] = c[2] = c[3] = c[5] = c[6] = c[7] = 0.0f;
        }
#pragma unroll
        for (int q = 0; q < 9; q++) g_cellm[q] = c[q];

        float a = c[0], b = c[1], cc = c[2];
        float d = c[3], e = c[4], f  = c[5];
        float g = c[6], h = c[7], i  = c[8];
        float A =  (e * i - f * h);
        float B = -(d * i - f * g);
        float C =  (d * h - e * g);
        float det = a * A + b * B + cc * C;
        float invdet = 1.0f / det;
        g_inv[0] = A * invdet;
        g_inv[1] = -(b * i - cc * h) * invdet;
        g_inv[2] =  (b * f - cc * e) * invdet;
        g_inv[3] = B * invdet;
        g_inv[4] =  (a * i - cc * g) * invdet;
        g_inv[5] = -(a * f - cc * d) * invdet;
        g_inv[6] = C * invdet;
        g_inv[7] = -(a * h - b * g) * invdet;
        g_inv[8] =  (a * e - b * d) * invdet;
        g_cell_zero = zero ? 1 : 0;
    }
}

__device__ __forceinline__ unsigned tri_off(unsigned i, unsigned T) {
    return (i * (T - i)) >> 1;   // i*(2n-1-i)/2
}

__global__ void __launch_bounds__(TPB)
nl_kernel(float* __restrict__ out, int n, unsigned P) {
    const unsigned t = blockIdx.x * TPB + threadIdx.x;
    const unsigned p = 4u * t;
    if (p >= P) return;

    const unsigned T = 2u * (unsigned)n - 1u;

    // ---- unrank p -> (i, j) ----
    const unsigned D = T * T - 8u * p;
    const float s = sqrtf((float)D);
    int i = (int)(((float)T - s) * 0.5f);
    if (i < 0) i = 0;
    if (i > n - 2) i = n - 2;
    unsigned offi = tri_off((unsigned)i, T);
    while (offi > p) { i--; offi = tri_off((unsigned)i, T); }
    unsigned rowend = tri_off((unsigned)(i + 1), T);
    while (rowend <= p && i < n - 2) {
        i++; offi = rowend; rowend = tri_off((unsigned)(i + 1), T);
    }
    int j = i + 1 + (int)(p - offi);

    // ---- hoist cell matrices into registers (once per 4 pairs) ----
    const int czero = g_cell_zero;
    float inv[9], cel[9];
    if (!czero) {
#pragma unroll
        for (int q = 0; q < 9; q++) { inv[q] = g_inv[q]; cel[q] = g_cellm[q]; }
    }

    float xi = g_x[i], yi = g_y[i], zi = g_z[i];

    float oi[4], oj[4], od[4], del[12];
    const unsigned nv = (P - p < 4u) ? (P - p) : 4u;

#pragma unroll
    for (int k = 0; k < 4; k++) {
        if ((unsigned)k >= nv) { oi[k] = oj[k] = od[k] = 0.0f;
                                 del[3*k] = del[3*k+1] = del[3*k+2] = 0.0f; continue; }
        if (p + (unsigned)k == rowend) {        // row crossing (rare)
            i++; j = i + 1;
            rowend = tri_off((unsigned)(i + 1), T);
            xi = g_x[i]; yi = g_y[i]; zi = g_z[i];
        }

        float dx = xi - g_x[j];
        float dy = yi - g_y[j];
        float dz = zi - g_z[j];

        if (!czero) {
            const float f0 = dx * inv[0] + dy * inv[3] + dz * inv[6];
            const float f1 = dx * inv[1] + dy * inv[4] + dz * inv[7];
            const float f2 = dx * inv[2] + dy * inv[5] + dz * inv[8];
            const float r0 = rintf(f0);   // jnp.round = half-to-even
            const float r1 = rintf(f1);
            const float r2 = rintf(f2);
            dx -= r0 * cel[0] + r1 * cel[3] + r2 * cel[6];
            dy -= r0 * cel[1] + r1 * cel[4] + r2 * cel[7];
            dz -= r0 * cel[2] + r1 * cel[5] + r2 * cel[8];
        }

        const float dist = sqrtf(dx * dx + dy * dy + dz * dz);
        const bool m = (dist <= 5.0f);

        oi[k] = m ? (float)i : -1.0f;
        oj[k] = m ? (float)j : -1.0f;
        od[k] = m ? dist : 0.0f;
        del[3*k + 0] = m ? dx : 0.0f;
        del[3*k + 1] = m ? dy : 0.0f;
        del[3*k + 2] = m ? dz : 0.0f;
        j++;
    }

    if (nv == 4u) {
        // all vector stores are 16B-aligned: P % 4 == 0, p % 4 == 0
        *reinterpret_cast<float4*>(out + p) =
            make_float4(oi[0], oi[1], oi[2], oi[3]);
        *reinterpret_cast<float4*>(out + (size_t)P + p) =
            make_float4(oj[0], oj[1], oj[2], oj[3]);
        *reinterpret_cast<float4*>(out + 5 * (size_t)P + p) =
            make_float4(od[0], od[1], od[2], od[3]);
        float* db = out + 2 * (size_t)P + 3 * (size_t)p;   // byte off 8P+48t, 16B-aligned
        *reinterpret_cast<float4*>(db + 0) = make_float4(del[0], del[1], del[2],  del[3]);
        *reinterpret_cast<float4*>(db + 4) = make_float4(del[4], del[5], del[6],  del[7]);
        *reinterpret_cast<float4*>(db + 8) = make_float4(del[8], del[9], del[10], del[11]);
    } else {
        for (unsigned k = 0; k < nv; k++) {
            out[p + k]                 = oi[k];
            out[(size_t)P + p + k]     = oj[k];
            out[5 * (size_t)P + p + k] = od[k];
            out[2 * (size_t)P + 3 * ((size_t)p + k) + 0] = del[3*k + 0];
            out[2 * (size_t)P + 3 * ((size_t)p + k) + 1] = del[3*k + 1];
            out[2 * (size_t)P + 3 * ((size_t)p + k) + 2] = del[3*k + 2];
        }
    }
}

extern "C" void kernel_launch(void* const* d_in, const int* in_sizes, int n_in,
                              void* d_out, int out_size) {
    const float* xyz  = (const float*)d_in[0];
    const float* cell = (const float*)d_in[1];
    if (n_in >= 2 && in_sizes[0] == 9 && in_sizes[1] != 9) {
        const float* t = xyz; xyz = cell; cell = t;
    }
    const int n = (in_sizes[0] == 9 && n_in >= 2) ? in_sizes[1] / 3 : in_sizes[0] / 3;
    const unsigned P = (unsigned)((size_t)n * (size_t)(n - 1) / 2);

    prep_kernel<<<(n + TPB - 1) / TPB, TPB>>>(xyz, cell, n);

    const unsigned nthreads = (P + 3) / 4;
    const unsigned blocks = (nthreads + TPB - 1) / TPB;
    nl_kernel<<<blocks, TPB>>>((float*)d_out, n, P);
}